// round 16
// baseline (speedup 1.0000x reference)
#include <cuda.h>
#include <cuda_runtime.h>
#include <cstdint>

// ----------------------------------------------------------------------------
// Walsh-Hadamard transform, N = 2^25 floats.
// pass1: element bits 0..13 (16K-float contiguous tiles)  [R7, unchanged]
// pass2: element bits 14..24 as 2048-row x 16384-col column transform.
//   R13: pass2 rebuilt with 1024 threads (32 warps/SM, was 16) to fix the
//   latency-bound compute slab ncu exposed (issue 26%, nothing saturated).
//   16 values/thread forces a 3-round butterfly schedule:
//     round A: row bits {7,8,9,10}   (i-pairs + pack)
//     round B: row bits {3,4,5,6}    (i-pairs + pack)
//     round C: row bits {0,1,2}      (shfl m8,m16 + pack)
//   Same persistent triple-buffered TMA pipeline as R10 (proven).
// Fallback: R7 LDG pass2 if tensor-map creation fails.
// ----------------------------------------------------------------------------

// ---------- packed f32x2 helpers ----------
__device__ __forceinline__ unsigned long long pack2(float x, float y) {
    unsigned long long u;
    asm("mov.b64 %0, {%1, %2};" : "=l"(u) : "f"(x), "f"(y));
    return u;
}
__device__ __forceinline__ void unpack2(unsigned long long u, float &x, float &y) {
    asm("mov.b64 {%0, %1}, %2;" : "=f"(x), "=f"(y) : "l"(u));
}
__device__ __forceinline__ unsigned long long add2(unsigned long long a, unsigned long long b) {
    unsigned long long r;
    asm("add.rn.f32x2 %0, %1, %2;" : "=l"(r) : "l"(a), "l"(b));
    return r;
}
__device__ __forceinline__ unsigned long long fma2(unsigned long long a, unsigned long long b,
                                                   unsigned long long c) {
    unsigned long long r;
    asm("fma.rn.f32x2 %0, %1, %2, %3;" : "=l"(r) : "l"(a), "l"(b), "l"(c));
    return r;
}
// a <- a+b ; b <- a-b
__device__ __forceinline__ void bflyp(unsigned long long &a, unsigned long long &b,
                                      unsigned long long NEG2) {
    unsigned long long s = add2(a, b);
    b = fma2(b, NEG2, s);
    a = s;
}
__device__ __forceinline__ unsigned long long bflyin(unsigned long long a) {
    float x, y;
    unpack2(a, x, y);
    return pack2(x + y, x - y);
}
__device__ __forceinline__ unsigned long long shflb(unsigned long long v, int mask,
                                                    unsigned long long S) {
    unsigned long long o = __shfl_xor_sync(0xffffffffu, v, mask);
    return fma2(v, S, o);
}
__device__ __forceinline__ uint32_t smem_u32(const void* p) {
    uint32_t a;
    asm("{ .reg .u64 t; cvta.to.shared.u64 t, %1; cvt.u32.u64 %0, t; }" : "=r"(a) : "l"(p));
    return a;
}
__device__ __forceinline__ void mbar_wait(uint32_t addr, uint32_t parity) {
    asm volatile(
        "{\n\t.reg .pred P1;\n\t"
        "WL_%=:\n\t"
        "mbarrier.try_wait.parity.acquire.cta.shared::cta.b64 P1, [%0], %1, 0x989680;\n\t"
        "@P1 bra.uni WD_%=;\n\t"
        "bra.uni WL_%=;\n\t"
        "WD_%=:\n\t}"
        :: "r"(addr), "r"(parity) : "memory");
}

// ----------------------------------------------------------------------------
// Pass 1: bits 0..13 (unchanged, passing, ~5.6 TB/s effective)
// ----------------------------------------------------------------------------
__global__ void __launch_bounds__(512, 2) wht_pass1(const float* __restrict__ x,
                                                    float* __restrict__ y) {
    extern __shared__ __align__(16) float s[];          // 16384 floats = 64 KB
    const int tid  = threadIdx.x;
    const int lane = tid & 31;
    const int base = blockIdx.x << 14;
    const unsigned long long NEG2 = pack2(-2.f, -2.f);

    unsigned long long v[16];

    // ---- Phase A: bits {0,1} + {11,12,13} + {5 shfl} ----
#pragma unroll
    for (int jj = 0; jj < 8; ++jj) {
        float4 f = *reinterpret_cast<const float4*>(x + base + 4 * tid + 2048 * jj);
        v[2 * jj]     = pack2(f.x, f.y);
        v[2 * jj + 1] = pack2(f.z, f.w);
    }
#pragma unroll
    for (int i = 0; i < 16; ++i) v[i] = bflyin(v[i]);                       // bit 0
#pragma unroll
    for (int jj = 0; jj < 8; ++jj) bflyp(v[2 * jj], v[2 * jj + 1], NEG2);   // bit 1
#pragma unroll
    for (int jj = 0; jj < 8; jj += 2) {                                     // bit 11
        bflyp(v[2 * jj],     v[2 * jj + 2], NEG2);
        bflyp(v[2 * jj + 1], v[2 * jj + 3], NEG2);
    }
#pragma unroll
    for (int g = 0; g < 8; g += 4)                                          // bit 12
#pragma unroll
        for (int jj = g; jj < g + 2; ++jj) {
            bflyp(v[2 * jj],     v[2 * jj + 4], NEG2);
            bflyp(v[2 * jj + 1], v[2 * jj + 5], NEG2);
        }
#pragma unroll
    for (int jj = 0; jj < 4; ++jj) {                                        // bit 13
        bflyp(v[2 * jj],     v[2 * jj + 8], NEG2);
        bflyp(v[2 * jj + 1], v[2 * jj + 9], NEG2);
    }
    {                                                                       // bit 5
        const float sg = (lane & 8) ? -1.f : 1.f;
        const unsigned long long S = pack2(sg, sg);
#pragma unroll
        for (int i = 0; i < 16; ++i) v[i] = shflb(v[i], 8, S);
    }
#pragma unroll
    for (int jj = 0; jj < 8; ++jj) {
        float a, b, c, d;
        unpack2(v[2 * jj], a, b);
        unpack2(v[2 * jj + 1], c, d);
        *reinterpret_cast<float4*>(s + 4 * tid + 2048 * jj) = make_float4(a, b, c, d);
    }
    __syncthreads();

    // ---- Phase B: bits {6..9} + {10 pack} + {2,3,4 shfl} ----
    const int w  = tid >> 5;
    const int eA = lane + 32 * (w & 1) + 2048 * (w >> 1);
#pragma unroll
    for (int i = 0; i < 16; ++i)
        v[i] = pack2(s[eA + 64 * i], s[eA + 64 * i + 1024]);
#pragma unroll
    for (int i = 0; i < 16; i += 2) bflyp(v[i], v[i + 1], NEG2);            // bit 6
#pragma unroll
    for (int i = 0; i < 16; i += 4) {                                       // bit 7
        bflyp(v[i],     v[i + 2], NEG2);
        bflyp(v[i + 1], v[i + 3], NEG2);
    }
#pragma unroll
    for (int g = 0; g < 16; g += 8)                                         // bit 8
#pragma unroll
        for (int i = g; i < g + 4; ++i) bflyp(v[i], v[i + 4], NEG2);
#pragma unroll
    for (int i = 0; i < 8; ++i) bflyp(v[i], v[i + 8], NEG2);                // bit 9
#pragma unroll
    for (int i = 0; i < 16; ++i) v[i] = bflyin(v[i]);                       // bit 10
#pragma unroll
    for (int m = 0; m < 3; ++m) {                                           // bits 2..4
        const int mask = 4 << m;
        const float sg = (lane & mask) ? -1.f : 1.f;
        const unsigned long long S = pack2(sg, sg);
#pragma unroll
        for (int i = 0; i < 16; ++i) v[i] = shflb(v[i], mask, S);
    }
#pragma unroll
    for (int i = 0; i < 16; ++i) {
        float a, b;
        unpack2(v[i], a, b);
        y[base + eA + 64 * i]        = a;
        y[base + eA + 64 * i + 1024] = b;
    }
}

// ----------------------------------------------------------------------------
// Pass 2 (TMA, persistent, triple-buffered, 1024 threads): bits 14..24.
// [2048 rows x 16384 cols]; stripe = 8 cols x 2048 rows = 64 KB; 2048 stripes.
// 32 warps/SM; 16 values (8 packed regs) per thread; 3 butterfly rounds:
//   A: r = rl + 128*i + 1024*p              -> bits {7,8,9} (i) + {10} (pack)
//   B: r = q + 4*(w&1) + 8*i + 64*p + 128*(w>>1)
//                                           -> bits {3,4,5} (i) + {6} (pack)
//   C: r = q + 4*p + 8*i + 64*w             -> bit {2} (pack) + {0,1} (shfl)
// c = tid&7; every phase's smem address = lane + const per warp (no conflicts).
// ----------------------------------------------------------------------------
__global__ void __launch_bounds__(1024, 1) wht_pass2_tma(const __grid_constant__ CUtensorMap tmap) {
    extern __shared__ __align__(16) float t[];          // 3*16384 floats + mbars
    uint64_t* mbar = reinterpret_cast<uint64_t*>(t + 3 * 16384);
    const int tid  = threadIdx.x;
    const int lane = tid & 31;
    const int c    = tid & 7;
    const unsigned long long NEG2 = pack2(-2.f, -2.f);
    const uint32_t ts  = smem_u32(t);
    const uint32_t mb0 = smem_u32(mbar);

    if (tid == 0) {
#pragma unroll
        for (int j = 0; j < 3; ++j)
            asm volatile("mbarrier.init.shared.b64 [%0], %1;"
                         :: "r"(mb0 + 8 * j), "r"(1) : "memory");
    }
    __syncthreads();

    const int nstripe = 2048;
    const int stride  = gridDim.x;
    int ph0 = 0, ph1 = 0, ph2 = 0;

    // prologue: load first stripe into buf 0
    if (tid == 0 && blockIdx.x < nstripe) {
        asm volatile("mbarrier.arrive.expect_tx.shared.b64 _, [%0], %1;"
                     :: "r"(mb0), "r"(65536u) : "memory");
        const int cx = blockIdx.x * 8;
#pragma unroll
        for (int kk = 0; kk < 8; ++kk)
            asm volatile(
                "cp.async.bulk.tensor.2d.shared::cta.global.tile.mbarrier::complete_tx::bytes "
                "[%0], [%1, {%2, %3}], [%4];"
                :: "r"(ts + kk * 8192), "l"(&tmap), "r"(cx), "r"(kk * 256), "r"(mb0)
                : "memory");
    }

    int k = 0;
    for (int sIdx = blockIdx.x; sIdx < nstripe; sIdx += stride, ++k) {
        const int b = k % 3;
        const uint32_t mb = mb0 + 8 * b;
        const uint32_t tbase = ts + (uint32_t)b * 65536u;
        float* tb = t + b * 16384;

        // wait current buffer full
        int ph = (b == 0) ? ph0 : (b == 1) ? ph1 : ph2;
        mbar_wait(mb, ph);
        if (b == 0) ph0 ^= 1; else if (b == 1) ph1 ^= 1; else ph2 ^= 1;

        // issue next stripe's load into buf (k+1)%3 (overlaps compute)
        const int snext = sIdx + stride;
        if (tid == 0 && snext < nstripe) {
            const int bn = (k + 1) % 3;
            const uint32_t mbn = mb0 + 8 * bn;
            const uint32_t tn  = ts + (uint32_t)bn * 65536u;
            // store that last used buf bn (iter k-2) must have drained
            asm volatile("cp.async.bulk.wait_group 1;" ::: "memory");
            asm volatile("mbarrier.arrive.expect_tx.shared.b64 _, [%0], %1;"
                         :: "r"(mbn), "r"(65536u) : "memory");
            const int cx = snext * 8;
#pragma unroll
            for (int kk = 0; kk < 8; ++kk)
                asm volatile(
                    "cp.async.bulk.tensor.2d.shared::cta.global.tile.mbarrier::complete_tx::bytes "
                    "[%0], [%1, {%2, %3}], [%4];"
                    :: "r"(tn + kk * 8192), "l"(&tmap), "r"(cx), "r"(kk * 256), "r"(mbn)
                    : "memory");
        }

        unsigned long long v[8];

        // ---- Round A: r = rl + 128*i + 1024*p ; bits {7,8,9} + {10 pack} ----
        const int rl = tid >> 3;                        // r bits 0..6
#pragma unroll
        for (int i = 0; i < 8; ++i)
            v[i] = pack2(tb[(rl + 128 * i) * 8 + c],
                         tb[(rl + 128 * i + 1024) * 8 + c]);
#pragma unroll
        for (int i = 0; i < 8; i += 2) bflyp(v[i], v[i + 1], NEG2);         // bit 7
#pragma unroll
        for (int i = 0; i < 8; i += 4) {                                    // bit 8
            bflyp(v[i],     v[i + 2], NEG2);
            bflyp(v[i + 1], v[i + 3], NEG2);
        }
#pragma unroll
        for (int i = 0; i < 4; ++i) bflyp(v[i], v[i + 4], NEG2);            // bit 9
#pragma unroll
        for (int i = 0; i < 8; ++i) v[i] = bflyin(v[i]);                    // bit 10
#pragma unroll
        for (int i = 0; i < 8; ++i) {
            float a, bq;
            unpack2(v[i], a, bq);
            tb[(rl + 128 * i) * 8 + c]        = a;
            tb[(rl + 128 * i + 1024) * 8 + c] = bq;
        }
        __syncthreads();

        // ---- Round B: r = q + 4*(w&1) + 8*i + 64*p + 128*(w>>1) ----
        //      bits {3,4,5} (i-pairs) + {6} (pack)
        const int q  = (lane >> 3) & 3;                 // r bits 0,1
        const int w  = tid >> 5;                        // 5 bits
        const int rB = q + 4 * (w & 1) + 128 * (w >> 1);
#pragma unroll
        for (int i = 0; i < 8; ++i)
            v[i] = pack2(tb[(rB + 8 * i) * 8 + c],
                         tb[(rB + 8 * i + 64) * 8 + c]);
#pragma unroll
        for (int i = 0; i < 8; i += 2) bflyp(v[i], v[i + 1], NEG2);         // bit 3
#pragma unroll
        for (int i = 0; i < 8; i += 4) {                                    // bit 4
            bflyp(v[i],     v[i + 2], NEG2);
            bflyp(v[i + 1], v[i + 3], NEG2);
        }
#pragma unroll
        for (int i = 0; i < 4; ++i) bflyp(v[i], v[i + 4], NEG2);            // bit 5
#pragma unroll
        for (int i = 0; i < 8; ++i) v[i] = bflyin(v[i]);                    // bit 6
#pragma unroll
        for (int i = 0; i < 8; ++i) {
            float a, bq;
            unpack2(v[i], a, bq);
            tb[(rB + 8 * i) * 8 + c]        = a;
            tb[(rB + 8 * i + 64) * 8 + c]   = bq;
        }
        __syncthreads();

        // ---- Round C: r = q + 4*p + 8*i + 64*w ; bit {2} pack + {0,1} shfl ----
        const int rC = q + 64 * w;
#pragma unroll
        for (int i = 0; i < 8; ++i)
            v[i] = pack2(tb[(rC + 8 * i) * 8 + c],
                         tb[(rC + 8 * i + 4) * 8 + c]);
#pragma unroll
        for (int i = 0; i < 8; ++i) v[i] = bflyin(v[i]);                    // bit 2
#pragma unroll
        for (int m = 0; m < 2; ++m) {                                       // bits 0,1
            const int mask = 8 << m;
            const float sg = (lane & mask) ? -1.f : 1.f;
            const unsigned long long S = pack2(sg, sg);
#pragma unroll
            for (int i = 0; i < 8; ++i) v[i] = shflb(v[i], mask, S);
        }
#pragma unroll
        for (int i = 0; i < 8; ++i) {
            float a, bq;
            unpack2(v[i], a, bq);
            tb[(rC + 8 * i) * 8 + c]        = a;
            tb[(rC + 8 * i + 4) * 8 + c]    = bq;
        }
        __syncthreads();

        // fire-and-forget TMA store of this stripe
        if (tid == 0) {
            asm volatile("fence.proxy.async.shared::cta;" ::: "memory");
            const int cx = sIdx * 8;
#pragma unroll
            for (int kk = 0; kk < 8; ++kk)
                asm volatile(
                    "cp.async.bulk.tensor.2d.global.shared::cta.tile.bulk_group "
                    "[%0, {%1, %2}], [%3];"
                    :: "l"(&tmap), "r"(cx), "r"(kk * 256), "r"(tbase + kk * 8192)
                    : "memory");
            asm volatile("cp.async.bulk.commit_group;" ::: "memory");
        }
        // no inline wait: next iteration's wait_group 1 gates buffer reuse
    }

    if (tid == 0)
        asm volatile("cp.async.bulk.wait_group 0;" ::: "memory");
    __syncthreads();
}

// ----------------------------------------------------------------------------
// Pass 2 (LDG fallback) - R7 kernel verbatim, known correct.
// ----------------------------------------------------------------------------
__global__ void __launch_bounds__(512, 2) wht_pass2_ldg(float* __restrict__ y) {
    extern __shared__ float t[];
    const int tid  = threadIdx.x;
    const int lane = tid & 31;
    const int c    = tid & 7;
    const int cb   = blockIdx.x * 8 + c;
    const unsigned long long NEG2 = pack2(-2.f, -2.f);

    unsigned long long v[16];

    const int rl = tid >> 3;
    {
        const float* src = y + cb + rl * 16384;
#pragma unroll
        for (int i = 0; i < 16; ++i) {
            float a = src[(64 * i) * 16384];
            float b = src[(64 * (i + 16)) * 16384];
            v[i] = pack2(a, b);
        }
    }
#pragma unroll
    for (int i = 0; i < 16; i += 2) bflyp(v[i], v[i + 1], NEG2);
#pragma unroll
    for (int i = 0; i < 16; i += 4) {
        bflyp(v[i],     v[i + 2], NEG2);
        bflyp(v[i + 1], v[i + 3], NEG2);
    }
#pragma unroll
    for (int g = 0; g < 16; g += 8)
#pragma unroll
        for (int i = g; i < g + 4; ++i) bflyp(v[i], v[i + 4], NEG2);
#pragma unroll
    for (int i = 0; i < 8; ++i) bflyp(v[i], v[i + 8], NEG2);
#pragma unroll
    for (int i = 0; i < 16; ++i) v[i] = bflyin(v[i]);
#pragma unroll
    for (int i = 0; i < 16; ++i) {
        float a, b;
        unpack2(v[i], a, b);
        t[(rl + 64 * i) * 8 + c]        = a;
        t[(rl + 64 * (i + 16)) * 8 + c] = b;
    }
    __syncthreads();

    const int q  = (lane >> 3) & 3;
    const int w  = tid >> 5;
    const int rb = q + 128 * w;
#pragma unroll
    for (int i = 0; i < 16; ++i)
        v[i] = pack2(t[(rb + 4 * i) * 8 + c],
                     t[(rb + 4 * (i + 16)) * 8 + c]);
#pragma unroll
    for (int i = 0; i < 16; i += 2) bflyp(v[i], v[i + 1], NEG2);
#pragma unroll
    for (int i = 0; i < 16; i += 4) {
        bflyp(v[i],     v[i + 2], NEG2);
        bflyp(v[i + 1], v[i + 3], NEG2);
    }
#pragma unroll
    for (int g = 0; g < 16; g += 8)
#pragma unroll
        for (int i = g; i < g + 4; ++i) bflyp(v[i], v[i + 4], NEG2);
#pragma unroll
    for (int i = 0; i < 8; ++i) bflyp(v[i], v[i + 8], NEG2);
#pragma unroll
    for (int m = 0; m < 2; ++m) {
        const int mask = 8 << m;
        const float sg = (lane & mask) ? -1.f : 1.f;
        const unsigned long long S = pack2(sg, sg);
#pragma unroll
        for (int i = 0; i < 16; ++i) v[i] = shflb(v[i], mask, S);
    }
    float* dst = y + cb;
#pragma unroll
    for (int i = 0; i < 16; ++i) {
        float a, b;
        unpack2(v[i], a, b);
        dst[(rb + 4 * i) * 16384]        = a;
        dst[(rb + 4 * (i + 16)) * 16384] = b;
    }
}

// ----------------------------------------------------------------------------
typedef CUresult (*PFN_encodeTiled)(
    CUtensorMap*, CUtensorMapDataType, cuuint32_t, void*,
    const cuuint64_t*, const cuuint64_t*, const cuuint32_t*, const cuuint32_t*,
    CUtensorMapInterleave, CUtensorMapSwizzle, CUtensorMapL2promotion,
    CUtensorMapFloatOOBfill);

extern "C" void kernel_launch(void* const* d_in, const int* in_sizes, int n_in,
                              void* d_out, int out_size) {
    (void)in_sizes; (void)n_in; (void)out_size;
    const float* x = (const float*)d_in[0];
    float* y = (float*)d_out;

    const int SMEM_P2 = 3 * 65536 + 32;   // 3 x 64KB buffers + mbarriers

    cudaFuncSetAttribute(wht_pass1,     cudaFuncAttributeMaxDynamicSharedMemorySize, 65536);
    cudaFuncSetAttribute(wht_pass2_tma, cudaFuncAttributeMaxDynamicSharedMemorySize, SMEM_P2);
    cudaFuncSetAttribute(wht_pass2_ldg, cudaFuncAttributeMaxDynamicSharedMemorySize, 65536);

    // Pass 1: bits 0..13
    wht_pass1<<<2048, 512, 65536>>>(x, y);

    // Build tensor map for pass 2 (runtime-resolved driver API; no -lcuda dep)
    bool tma_ok = false;
    CUtensorMap tmap;
    {
        void* fp = nullptr;
        cudaDriverEntryPointQueryResult qr = cudaDriverEntryPointSymbolNotFound;
        if (cudaGetDriverEntryPointByVersion("cuTensorMapEncodeTiled", &fp, 12000,
                                             cudaEnableDefault, &qr) == cudaSuccess &&
            qr == cudaDriverEntryPointSuccess && fp) {
            PFN_encodeTiled enc = (PFN_encodeTiled)fp;
            cuuint64_t dims[2]    = {16384, 2048};
            cuuint64_t strides[1] = {16384ull * 4ull};
            cuuint32_t box[2]     = {8, 256};
            cuuint32_t es[2]      = {1, 1};
            tma_ok = (enc(&tmap, CU_TENSOR_MAP_DATA_TYPE_FLOAT32, 2, y,
                          dims, strides, box, es,
                          CU_TENSOR_MAP_INTERLEAVE_NONE, CU_TENSOR_MAP_SWIZZLE_NONE,
                          CU_TENSOR_MAP_L2_PROMOTION_L2_128B,
                          CU_TENSOR_MAP_FLOAT_OOB_FILL_NONE) == CUDA_SUCCESS);
        }
    }

    // Pass 2: bits 14..24
    if (tma_ok) {
        int nsm = 148;
        cudaDeviceGetAttribute(&nsm, cudaDevAttrMultiProcessorCount, 0);
        wht_pass2_tma<<<nsm, 1024, SMEM_P2>>>(tmap);
    } else {
        wht_pass2_ldg<<<2048, 512, 65536>>>(y);
    }
}

// round 17
// speedup vs baseline: 1.4982x; 1.4982x over previous
#include <cuda.h>
#include <cuda_runtime.h>
#include <cstdint>

// ----------------------------------------------------------------------------
// Walsh-Hadamard transform, N = 2^25 floats.
// pass1: element bits 0..13 (16K-float contiguous tiles)  [R7, unchanged]
// pass2: element bits 14..24 as 2048-row x 16384-col column transform.
//   R16: R10's proven persistent triple-buffered TMA pipeline, with the
//   compute slab repacked COLUMN-wise: each thread owns an adjacent column
//   pair (f32x2) and 16 rows, so smem traffic is LDS.64/STS.64 (half the
//   instructions of R10) and every butterfly is a packed op (no bflyin).
//   Two phases: A = row bits {7..10}, B = {3..6} + {0,1,2 shfl}.
// Fallback: R7 LDG pass2 if tensor-map creation fails.
// ----------------------------------------------------------------------------

// ---------- packed f32x2 helpers ----------
__device__ __forceinline__ unsigned long long pack2(float x, float y) {
    unsigned long long u;
    asm("mov.b64 %0, {%1, %2};" : "=l"(u) : "f"(x), "f"(y));
    return u;
}
__device__ __forceinline__ void unpack2(unsigned long long u, float &x, float &y) {
    asm("mov.b64 {%0, %1}, %2;" : "=f"(x), "=f"(y) : "l"(u));
}
__device__ __forceinline__ unsigned long long add2(unsigned long long a, unsigned long long b) {
    unsigned long long r;
    asm("add.rn.f32x2 %0, %1, %2;" : "=l"(r) : "l"(a), "l"(b));
    return r;
}
__device__ __forceinline__ unsigned long long fma2(unsigned long long a, unsigned long long b,
                                                   unsigned long long c) {
    unsigned long long r;
    asm("fma.rn.f32x2 %0, %1, %2, %3;" : "=l"(r) : "l"(a), "l"(b), "l"(c));
    return r;
}
// a <- a+b ; b <- a-b
__device__ __forceinline__ void bflyp(unsigned long long &a, unsigned long long &b,
                                      unsigned long long NEG2) {
    unsigned long long s = add2(a, b);
    b = fma2(b, NEG2, s);
    a = s;
}
__device__ __forceinline__ unsigned long long bflyin(unsigned long long a) {
    float x, y;
    unpack2(a, x, y);
    return pack2(x + y, x - y);
}
__device__ __forceinline__ unsigned long long shflb(unsigned long long v, int mask,
                                                    unsigned long long S) {
    unsigned long long o = __shfl_xor_sync(0xffffffffu, v, mask);
    return fma2(v, S, o);
}
__device__ __forceinline__ uint32_t smem_u32(const void* p) {
    uint32_t a;
    asm("{ .reg .u64 t; cvta.to.shared.u64 t, %1; cvt.u32.u64 %0, t; }" : "=r"(a) : "l"(p));
    return a;
}
__device__ __forceinline__ void mbar_wait(uint32_t addr, uint32_t parity) {
    asm volatile(
        "{\n\t.reg .pred P1;\n\t"
        "WL_%=:\n\t"
        "mbarrier.try_wait.parity.acquire.cta.shared::cta.b64 P1, [%0], %1, 0x989680;\n\t"
        "@P1 bra.uni WD_%=;\n\t"
        "bra.uni WL_%=;\n\t"
        "WD_%=:\n\t}"
        :: "r"(addr), "r"(parity) : "memory");
}

// ----------------------------------------------------------------------------
// Pass 1: bits 0..13 (unchanged, passing, ~5.6 TB/s effective)
// ----------------------------------------------------------------------------
__global__ void __launch_bounds__(512, 2) wht_pass1(const float* __restrict__ x,
                                                    float* __restrict__ y) {
    extern __shared__ __align__(16) float s[];          // 16384 floats = 64 KB
    const int tid  = threadIdx.x;
    const int lane = tid & 31;
    const int base = blockIdx.x << 14;
    const unsigned long long NEG2 = pack2(-2.f, -2.f);

    unsigned long long v[16];

    // ---- Phase A: bits {0,1} + {11,12,13} + {5 shfl} ----
#pragma unroll
    for (int jj = 0; jj < 8; ++jj) {
        float4 f = *reinterpret_cast<const float4*>(x + base + 4 * tid + 2048 * jj);
        v[2 * jj]     = pack2(f.x, f.y);
        v[2 * jj + 1] = pack2(f.z, f.w);
    }
#pragma unroll
    for (int i = 0; i < 16; ++i) v[i] = bflyin(v[i]);                       // bit 0
#pragma unroll
    for (int jj = 0; jj < 8; ++jj) bflyp(v[2 * jj], v[2 * jj + 1], NEG2);   // bit 1
#pragma unroll
    for (int jj = 0; jj < 8; jj += 2) {                                     // bit 11
        bflyp(v[2 * jj],     v[2 * jj + 2], NEG2);
        bflyp(v[2 * jj + 1], v[2 * jj + 3], NEG2);
    }
#pragma unroll
    for (int g = 0; g < 8; g += 4)                                          // bit 12
#pragma unroll
        for (int jj = g; jj < g + 2; ++jj) {
            bflyp(v[2 * jj],     v[2 * jj + 4], NEG2);
            bflyp(v[2 * jj + 1], v[2 * jj + 5], NEG2);
        }
#pragma unroll
    for (int jj = 0; jj < 4; ++jj) {                                        // bit 13
        bflyp(v[2 * jj],     v[2 * jj + 8], NEG2);
        bflyp(v[2 * jj + 1], v[2 * jj + 9], NEG2);
    }
    {                                                                       // bit 5
        const float sg = (lane & 8) ? -1.f : 1.f;
        const unsigned long long S = pack2(sg, sg);
#pragma unroll
        for (int i = 0; i < 16; ++i) v[i] = shflb(v[i], 8, S);
    }
#pragma unroll
    for (int jj = 0; jj < 8; ++jj) {
        float a, b, c, d;
        unpack2(v[2 * jj], a, b);
        unpack2(v[2 * jj + 1], c, d);
        *reinterpret_cast<float4*>(s + 4 * tid + 2048 * jj) = make_float4(a, b, c, d);
    }
    __syncthreads();

    // ---- Phase B: bits {6..9} + {10 pack} + {2,3,4 shfl} ----
    const int w  = tid >> 5;
    const int eA = lane + 32 * (w & 1) + 2048 * (w >> 1);
#pragma unroll
    for (int i = 0; i < 16; ++i)
        v[i] = pack2(s[eA + 64 * i], s[eA + 64 * i + 1024]);
#pragma unroll
    for (int i = 0; i < 16; i += 2) bflyp(v[i], v[i + 1], NEG2);            // bit 6
#pragma unroll
    for (int i = 0; i < 16; i += 4) {                                       // bit 7
        bflyp(v[i],     v[i + 2], NEG2);
        bflyp(v[i + 1], v[i + 3], NEG2);
    }
#pragma unroll
    for (int g = 0; g < 16; g += 8)                                         // bit 8
#pragma unroll
        for (int i = g; i < g + 4; ++i) bflyp(v[i], v[i + 4], NEG2);
#pragma unroll
    for (int i = 0; i < 8; ++i) bflyp(v[i], v[i + 8], NEG2);                // bit 9
#pragma unroll
    for (int i = 0; i < 16; ++i) v[i] = bflyin(v[i]);                       // bit 10
#pragma unroll
    for (int m = 0; m < 3; ++m) {                                           // bits 2..4
        const int mask = 4 << m;
        const float sg = (lane & mask) ? -1.f : 1.f;
        const unsigned long long S = pack2(sg, sg);
#pragma unroll
        for (int i = 0; i < 16; ++i) v[i] = shflb(v[i], mask, S);
    }
#pragma unroll
    for (int i = 0; i < 16; ++i) {
        float a, b;
        unpack2(v[i], a, b);
        y[base + eA + 64 * i]        = a;
        y[base + eA + 64 * i + 1024] = b;
    }
}

// ----------------------------------------------------------------------------
// Pass 2 (TMA, persistent, triple-buffered, column-packed): bits 14..24.
// [2048 rows x 16384 cols]; stripe = 8 cols x 2048 rows = 64 KB; 2048 stripes.
// 512 threads; each thread owns column pair cp (f32x2) and 16 rows per phase.
//   Phase A: r = (tid>>2) + 128*i      -> row bits {7,8,9,10} via i-pairs
//   Phase B: r = (lane>>2) + 8*i + 128*(tid>>5)
//                                      -> bits {3,4,5,6} i-pairs, {0,1,2} shfl
// smem access = float2 at (r*8 + 2*cp): per warp 64 consecutive words ->
// conflict-free LDS.64/STS.64.  TMA plumbing identical to R10 (proven).
// ----------------------------------------------------------------------------
__global__ void __launch_bounds__(512, 1) wht_pass2_tma(const __grid_constant__ CUtensorMap tmap) {
    extern __shared__ __align__(16) float t[];          // 3*16384 floats + mbars
    uint64_t* mbar = reinterpret_cast<uint64_t*>(t + 3 * 16384);
    const int tid  = threadIdx.x;
    const int lane = tid & 31;
    const unsigned long long NEG2 = pack2(-2.f, -2.f);
    const uint32_t ts  = smem_u32(t);
    const uint32_t mb0 = smem_u32(mbar);

    if (tid == 0) {
#pragma unroll
        for (int j = 0; j < 3; ++j)
            asm volatile("mbarrier.init.shared.b64 [%0], %1;"
                         :: "r"(mb0 + 8 * j), "r"(1) : "memory");
    }
    __syncthreads();

    const int nstripe = 2048;
    const int stride  = gridDim.x;
    int ph0 = 0, ph1 = 0, ph2 = 0;

    // prologue: load first stripe into buf 0
    if (tid == 0 && blockIdx.x < nstripe) {
        asm volatile("mbarrier.arrive.expect_tx.shared.b64 _, [%0], %1;"
                     :: "r"(mb0), "r"(65536u) : "memory");
        const int cx = blockIdx.x * 8;
#pragma unroll
        for (int kk = 0; kk < 8; ++kk)
            asm volatile(
                "cp.async.bulk.tensor.2d.shared::cta.global.tile.mbarrier::complete_tx::bytes "
                "[%0], [%1, {%2, %3}], [%4];"
                :: "r"(ts + kk * 8192), "l"(&tmap), "r"(cx), "r"(kk * 256), "r"(mb0)
                : "memory");
    }

    int k = 0;
    for (int sIdx = blockIdx.x; sIdx < nstripe; sIdx += stride, ++k) {
        const int b = k % 3;
        const uint32_t mb = mb0 + 8 * b;
        const uint32_t tbase = ts + (uint32_t)b * 65536u;
        float* tb = t + b * 16384;

        // wait current buffer full
        int ph = (b == 0) ? ph0 : (b == 1) ? ph1 : ph2;
        mbar_wait(mb, ph);
        if (b == 0) ph0 ^= 1; else if (b == 1) ph1 ^= 1; else ph2 ^= 1;

        // issue next stripe's load into buf (k+1)%3 (overlaps compute)
        const int snext = sIdx + stride;
        if (tid == 0 && snext < nstripe) {
            const int bn = (k + 1) % 3;
            const uint32_t mbn = mb0 + 8 * bn;
            const uint32_t tn  = ts + (uint32_t)bn * 65536u;
            // store that last used buf bn (iter k-2) must have drained
            asm volatile("cp.async.bulk.wait_group 1;" ::: "memory");
            asm volatile("mbarrier.arrive.expect_tx.shared.b64 _, [%0], %1;"
                         :: "r"(mbn), "r"(65536u) : "memory");
            const int cx = snext * 8;
#pragma unroll
            for (int kk = 0; kk < 8; ++kk)
                asm volatile(
                    "cp.async.bulk.tensor.2d.shared::cta.global.tile.mbarrier::complete_tx::bytes "
                    "[%0], [%1, {%2, %3}], [%4];"
                    :: "r"(tn + kk * 8192), "l"(&tmap), "r"(cx), "r"(kk * 256), "r"(mbn)
                    : "memory");
        }

        unsigned long long v[16];

        // ---- Phase A: r = rl + 128*i ; row bits {7,8,9,10} via i-pairs ----
        const int rl  = tid >> 2;                        // row bits 0..6
        const int cp2 = (tid & 3) * 2;                   // column (even)
        float2* tb2A = reinterpret_cast<float2*>(tb + rl * 8 + cp2);
#pragma unroll
        for (int i = 0; i < 16; ++i) {
            float2 f = tb2A[i * 512];                    // (128*i rows)*8/2 floats2
            v[i] = pack2(f.x, f.y);
        }
#pragma unroll
        for (int i = 0; i < 16; i += 2) bflyp(v[i], v[i + 1], NEG2);        // bit 7
#pragma unroll
        for (int i = 0; i < 16; i += 4) {                                   // bit 8
            bflyp(v[i],     v[i + 2], NEG2);
            bflyp(v[i + 1], v[i + 3], NEG2);
        }
#pragma unroll
        for (int g = 0; g < 16; g += 8)                                     // bit 9
#pragma unroll
            for (int i = g; i < g + 4; ++i) bflyp(v[i], v[i + 4], NEG2);
#pragma unroll
        for (int i = 0; i < 8; ++i) bflyp(v[i], v[i + 8], NEG2);            // bit 10
#pragma unroll
        for (int i = 0; i < 16; ++i) {
            float a, bq;
            unpack2(v[i], a, bq);
            tb2A[i * 512] = make_float2(a, bq);
        }
        __syncthreads();

        // ---- Phase B: r = q + 8*i + 128*w ; bits {3..6} i-pairs + {0,1,2} shfl ----
        const int q  = lane >> 2;                        // row bits 0..2
        const int w  = tid >> 5;                         // row bits 7..10
        float2* tb2B = reinterpret_cast<float2*>(tb + (q + 128 * w) * 8 + cp2);
#pragma unroll
        for (int i = 0; i < 16; ++i) {
            float2 f = tb2B[i * 32];                     // (8*i rows)*8/2 floats2
            v[i] = pack2(f.x, f.y);
        }
#pragma unroll
        for (int i = 0; i < 16; i += 2) bflyp(v[i], v[i + 1], NEG2);        // bit 3
#pragma unroll
        for (int i = 0; i < 16; i += 4) {                                   // bit 4
            bflyp(v[i],     v[i + 2], NEG2);
            bflyp(v[i + 1], v[i + 3], NEG2);
        }
#pragma unroll
        for (int g = 0; g < 16; g += 8)                                     // bit 5
#pragma unroll
            for (int i = g; i < g + 4; ++i) bflyp(v[i], v[i + 4], NEG2);
#pragma unroll
        for (int i = 0; i < 8; ++i) bflyp(v[i], v[i + 8], NEG2);            // bit 6
#pragma unroll
        for (int m = 0; m < 3; ++m) {                                       // bits 0,1,2
            const int mask = 4 << m;
            const float sg = (lane & mask) ? -1.f : 1.f;
            const unsigned long long S = pack2(sg, sg);
#pragma unroll
            for (int i = 0; i < 16; ++i) v[i] = shflb(v[i], mask, S);
        }
#pragma unroll
        for (int i = 0; i < 16; ++i) {
            float a, bq;
            unpack2(v[i], a, bq);
            tb2B[i * 32] = make_float2(a, bq);
        }
        __syncthreads();

        // fire-and-forget TMA store of this stripe
        if (tid == 0) {
            asm volatile("fence.proxy.async.shared::cta;" ::: "memory");
            const int cx = sIdx * 8;
#pragma unroll
            for (int kk = 0; kk < 8; ++kk)
                asm volatile(
                    "cp.async.bulk.tensor.2d.global.shared::cta.tile.bulk_group "
                    "[%0, {%1, %2}], [%3];"
                    :: "l"(&tmap), "r"(cx), "r"(kk * 256), "r"(tbase + kk * 8192)
                    : "memory");
            asm volatile("cp.async.bulk.commit_group;" ::: "memory");
        }
        // no inline wait: next iteration's wait_group 1 gates buffer reuse
    }

    if (tid == 0)
        asm volatile("cp.async.bulk.wait_group 0;" ::: "memory");
    __syncthreads();
}

// ----------------------------------------------------------------------------
// Pass 2 (LDG fallback) - R7 kernel verbatim, known correct.
// ----------------------------------------------------------------------------
__global__ void __launch_bounds__(512, 2) wht_pass2_ldg(float* __restrict__ y) {
    extern __shared__ float t[];
    const int tid  = threadIdx.x;
    const int lane = tid & 31;
    const int c    = tid & 7;
    const int cb   = blockIdx.x * 8 + c;
    const unsigned long long NEG2 = pack2(-2.f, -2.f);

    unsigned long long v[16];

    const int rl = tid >> 3;
    {
        const float* src = y + cb + rl * 16384;
#pragma unroll
        for (int i = 0; i < 16; ++i) {
            float a = src[(64 * i) * 16384];
            float b = src[(64 * (i + 16)) * 16384];
            v[i] = pack2(a, b);
        }
    }
#pragma unroll
    for (int i = 0; i < 16; i += 2) bflyp(v[i], v[i + 1], NEG2);
#pragma unroll
    for (int i = 0; i < 16; i += 4) {
        bflyp(v[i],     v[i + 2], NEG2);
        bflyp(v[i + 1], v[i + 3], NEG2);
    }
#pragma unroll
    for (int g = 0; g < 16; g += 8)
#pragma unroll
        for (int i = g; i < g + 4; ++i) bflyp(v[i], v[i + 4], NEG2);
#pragma unroll
    for (int i = 0; i < 8; ++i) bflyp(v[i], v[i + 8], NEG2);
#pragma unroll
    for (int i = 0; i < 16; ++i) v[i] = bflyin(v[i]);
#pragma unroll
    for (int i = 0; i < 16; ++i) {
        float a, b;
        unpack2(v[i], a, b);
        t[(rl + 64 * i) * 8 + c]        = a;
        t[(rl + 64 * (i + 16)) * 8 + c] = b;
    }
    __syncthreads();

    const int q  = (lane >> 3) & 3;
    const int w  = tid >> 5;
    const int rb = q + 128 * w;
#pragma unroll
    for (int i = 0; i < 16; ++i)
        v[i] = pack2(t[(rb + 4 * i) * 8 + c],
                     t[(rb + 4 * (i + 16)) * 8 + c]);
#pragma unroll
    for (int i = 0; i < 16; i += 2) bflyp(v[i], v[i + 1], NEG2);
#pragma unroll
    for (int i = 0; i < 16; i += 4) {
        bflyp(v[i],     v[i + 2], NEG2);
        bflyp(v[i + 1], v[i + 3], NEG2);
    }
#pragma unroll
    for (int g = 0; g < 16; g += 8)
#pragma unroll
        for (int i = g; i < g + 4; ++i) bflyp(v[i], v[i + 4], NEG2);
#pragma unroll
    for (int i = 0; i < 8; ++i) bflyp(v[i], v[i + 8], NEG2);
#pragma unroll
    for (int m = 0; m < 2; ++m) {
        const int mask = 8 << m;
        const float sg = (lane & mask) ? -1.f : 1.f;
        const unsigned long long S = pack2(sg, sg);
#pragma unroll
        for (int i = 0; i < 16; ++i) v[i] = shflb(v[i], mask, S);
    }
    float* dst = y + cb;
#pragma unroll
    for (int i = 0; i < 16; ++i) {
        float a, b;
        unpack2(v[i], a, b);
        dst[(rb + 4 * i) * 16384]        = a;
        dst[(rb + 4 * (i + 16)) * 16384] = b;
    }
}

// ----------------------------------------------------------------------------
typedef CUresult (*PFN_encodeTiled)(
    CUtensorMap*, CUtensorMapDataType, cuuint32_t, void*,
    const cuuint64_t*, const cuuint64_t*, const cuuint32_t*, const cuuint32_t*,
    CUtensorMapInterleave, CUtensorMapSwizzle, CUtensorMapL2promotion,
    CUtensorMapFloatOOBfill);

extern "C" void kernel_launch(void* const* d_in, const int* in_sizes, int n_in,
                              void* d_out, int out_size) {
    (void)in_sizes; (void)n_in; (void)out_size;
    const float* x = (const float*)d_in[0];
    float* y = (float*)d_out;

    const int SMEM_P2 = 3 * 65536 + 32;   // 3 x 64KB buffers + mbarriers

    cudaFuncSetAttribute(wht_pass1,     cudaFuncAttributeMaxDynamicSharedMemorySize, 65536);
    cudaFuncSetAttribute(wht_pass2_tma, cudaFuncAttributeMaxDynamicSharedMemorySize, SMEM_P2);
    cudaFuncSetAttribute(wht_pass2_ldg, cudaFuncAttributeMaxDynamicSharedMemorySize, 65536);

    // Pass 1: bits 0..13
    wht_pass1<<<2048, 512, 65536>>>(x, y);

    // Build tensor map for pass 2 (runtime-resolved driver API; no -lcuda dep)
    bool tma_ok = false;
    CUtensorMap tmap;
    {
        void* fp = nullptr;
        cudaDriverEntryPointQueryResult qr = cudaDriverEntryPointSymbolNotFound;
        if (cudaGetDriverEntryPointByVersion("cuTensorMapEncodeTiled", &fp, 12000,
                                             cudaEnableDefault, &qr) == cudaSuccess &&
            qr == cudaDriverEntryPointSuccess && fp) {
            PFN_encodeTiled enc = (PFN_encodeTiled)fp;
            cuuint64_t dims[2]    = {16384, 2048};
            cuuint64_t strides[1] = {16384ull * 4ull};
            cuuint32_t box[2]     = {8, 256};
            cuuint32_t es[2]      = {1, 1};
            tma_ok = (enc(&tmap, CU_TENSOR_MAP_DATA_TYPE_FLOAT32, 2, y,
                          dims, strides, box, es,
                          CU_TENSOR_MAP_INTERLEAVE_NONE, CU_TENSOR_MAP_SWIZZLE_NONE,
                          CU_TENSOR_MAP_L2_PROMOTION_L2_128B,
                          CU_TENSOR_MAP_FLOAT_OOB_FILL_NONE) == CUDA_SUCCESS);
        }
    }

    // Pass 2: bits 14..24
    if (tma_ok) {
        int nsm = 148;
        cudaDeviceGetAttribute(&nsm, cudaDevAttrMultiProcessorCount, 0);
        wht_pass2_tma<<<nsm, 512, SMEM_P2>>>(tmap);
    } else {
        wht_pass2_ldg<<<2048, 512, 65536>>>(y);
    }
}